// round 6
// baseline (speedup 1.0000x reference)
#include <cuda_runtime.h>
#include <cstdint>

#define L2E 1.4426950408889634f
#define BMAX 131072

// ---------------- device scratch (static, no runtime alloc) ----------------
__device__ float g_h[128u * BMAX];      // h^T, channel-major [128][B]
__device__ float g_z[20u * BMAX];       // z~^T, channel-major [20][B]
__device__ float g_stat1[256];          // sum[128], sumsq[128] of h
__device__ float g_stat2[20];           // sumsq[20] of z~
__device__ float g_Wf[128 * 20];        // folded weights, layout [c][j]
__device__ float g_s2[20], g_t2[20];    // BN2 affine
__device__ float4 g_fz[200];            // (centre, au, al, 0) per (rule, dim)
__device__ float g_wr[10];              // head weight * 0.5/FIN
__device__ float g_b0;                  // head bias

__device__ __forceinline__ float ex2f(float x) {
    float y; asm("ex2.approx.ftz.f32 %0, %1;" : "=f"(y) : "f"(x)); return y;
}

#define FMA_F32X2(d, a, b, c) \
    asm("fma.rn.f32x2 %0, %1, %2, %3;" : "=l"(d) : "l"(a), "l"(b), "l"(c))
#define PACK_DUP(d, f) \
    asm("mov.b64 %0, {%1, %1};" : "=l"(d) : "f"(f))
#define UNPACK2(lo, hi, v) \
    asm("mov.b64 {%0, %1}, %2;" : "=f"(lo), "=f"(hi) : "l"(v))

// ---------------- K0: zero accumulators ----------------
__global__ void k0_zero() {
    int t = threadIdx.x;
    if (t < 256) g_stat1[t] = 0.f;
    if (t < 20)  g_stat2[t] = 0.f;
}

// ---------------- K1: h = group-KAN(x), accumulate BN1 stats ----------------
// thread slot = (row-stream, group). slot%8 = group, slot/8 = starting row.
// Projection weights live in SMEM (layout [o*8+f][g] -> conflict-free LDS,
// 8 banks x 4-way broadcast), RBF coefficients stay in registers.
__global__ __launch_bounds__(256, 2) void k1_kan(
    const float* __restrict__ x,
    const float* __restrict__ centres,   // [8][8]
    const float* __restrict__ logw,      // [8][8]
    const float* __restrict__ rbw,       // [8][8]
    const float* __restrict__ linw,      // [8]
    const float* __restrict__ pW,        // [8][16][8]
    const float* __restrict__ pb,        // [8][16]
    int B, int rowsInFlight)
{
    __shared__ float pw_s[128][8];       // [o*8+f][g]
    __shared__ float pb_s[16][8];        // [o][g]
    for (int i = threadIdx.x; i < 1024; i += 256) {
        int g = i / 128, of = i % 128;   // pW index: g*128 + of
        pw_s[of][g] = pW[i];
    }
    if (threadIdx.x < 128) {
        int g = threadIdx.x / 16, o = threadIdx.x % 16;
        pb_s[o][g] = pb[g * 16 + o];
    }

    int slot = blockIdx.x * 256 + threadIdx.x;
    int g = slot & 7;
    int row0 = slot >> 3;

    float A[8], Bc[8], Gc[8], W[8];
#pragma unroll
    for (int k = 0; k < 8; k++) {
        float sig = __expf(logw[g * 8 + k]) + 1e-6f;
        float inv2 = 1.f / (sig * sig);
        float cc = centres[g * 8 + k];
        A[k] = -0.5f * L2E * inv2;
        Bc[k] = L2E * cc * inv2;
        Gc[k] = -0.5f * L2E * cc * cc * inv2;
        W[k] = rbw[g * 8 + k];
    }
    float lw = linw[g];

    float s[16], q[16];
#pragma unroll
    for (int o = 0; o < 16; o++) { s[o] = 0.f; q[o] = 0.f; }

    __syncthreads();

    for (int row = row0; row < B; row += rowsInFlight) {
        const float4* xv = reinterpret_cast<const float4*>(x + (size_t)row * 64 + g * 8);
        float4 xa = xv[0], xb = xv[1];
        float xf[8] = {xa.x, xa.y, xa.z, xa.w, xb.x, xb.y, xb.z, xb.w};
        float act[8];
#pragma unroll
        for (int f = 0; f < 8; f++) {
            float xvv = xf[f];
            float x2 = xvv * xvv;
            float acc = 0.f;
#pragma unroll
            for (int k = 0; k < 8; k++) {
                float arg = fmaf(A[k], x2, fmaf(Bc[k], xvv, Gc[k]));
                acc = fmaf(W[k], ex2f(arg), acc);
            }
            act[f] = fmaf(lw, xvv, acc);
        }
#pragma unroll
        for (int o = 0; o < 16; o++) {
            float p = pb_s[o][g];
#pragma unroll
            for (int f = 0; f < 8; f++)
                p = fmaf(act[f], pw_s[o * 8 + f][g], p);
            g_h[(size_t)(g * 16 + o) * B + row] = p;
            s[o] += p;
            q[o] = fmaf(p, p, q[o]);
        }
    }

    // reduce across the 4 lanes sharing the same group (xor 8, 16)
#pragma unroll
    for (int o = 0; o < 16; o++) {
        s[o] += __shfl_xor_sync(0xffffffffu, s[o], 8);
        s[o] += __shfl_xor_sync(0xffffffffu, s[o], 16);
        q[o] += __shfl_xor_sync(0xffffffffu, q[o], 8);
        q[o] += __shfl_xor_sync(0xffffffffu, q[o], 16);
    }
    __shared__ float sm[256];
    sm[threadIdx.x] = 0.f;
    __syncthreads();
    if ((threadIdx.x & 31) < 8) {
#pragma unroll
        for (int o = 0; o < 16; o++) {
            atomicAdd(&sm[g * 16 + o], s[o]);
            atomicAdd(&sm[128 + g * 16 + o], q[o]);
        }
    }
    __syncthreads();
    atomicAdd(&g_stat1[threadIdx.x], sm[threadIdx.x]);
}

// ---------------- K2: fold BN1 into Wf; fuzzy/head precompute ----------------
__global__ void k2_fold(
    const float* __restrict__ g1,        // bn1_gamma [128]
    const float* __restrict__ fpW,       // [20][128]
    const float* __restrict__ fzc,       // [10][20]
    const float* __restrict__ lsu,       // [10][20]
    const float* __restrict__ lsl,       // [10][20]
    const float* __restrict__ hW,        // [1][10]
    const float* __restrict__ hb,        // [1]
    float invB)
{
    __shared__ float s1sh[128];
    int t = threadIdx.x;
    if (t < 128) {
        float mu = g_stat1[t] * invB;
        float var = fmaf(-mu, mu, g_stat1[128 + t] * invB);
        s1sh[t] = g1[t] * rsqrtf(var + 1e-5f);
    }
    __syncthreads();
    for (int i = t; i < 2560; i += blockDim.x) {
        int c = i / 20, j = i % 20;
        g_Wf[i] = fpW[j * 128 + c] * s1sh[c];
    }
    for (int i = t; i < 200; i += blockDim.x) {
        float su = __expf(lsu[i]) + 1e-6f;
        float sl = fminf(__expf(lsl[i]) + 1e-6f, 0.9f * su);
        float4 v;
        v.x = fzc[i];
        v.y = -0.5f * L2E / (su * su);
        v.z = -0.5f * L2E / (sl * sl);
        v.w = 0.f;
        g_fz[i] = v;
    }
    if (t < 10) g_wr[t] = hW[t] * (0.5f / 20.f);
    if (t == 0) g_b0 = hb[0];
}

// ---------------- K3: z~ = h @ Wf^T (f32x2 packed), sumsq(z~) stats --------
// ONE row per thread: grid = B/256 blocks of 256 threads.
__global__ __launch_bounds__(256) void k3_gemm(int B) {
    __shared__ float ws[2560];           // Wf [c][j]
    __shared__ float sq[20];
    for (int i = threadIdx.x; i < 2560; i += 256) ws[i] = g_Wf[i];
    if (threadIdx.x < 20) sq[threadIdx.x] = 0.f;
    __syncthreads();
    const ulonglong2* wp = reinterpret_cast<const ulonglong2*>(ws);

    int row = blockIdx.x * 256 + threadIdx.x;

    unsigned long long a0[10];
#pragma unroll
    for (int p = 0; p < 10; p++) a0[p] = 0ull;

#pragma unroll 16
    for (int c = 0; c < 128; c++) {
        float h = g_h[(size_t)c * B + row];
        unsigned long long d0;
        PACK_DUP(d0, h);
#pragma unroll
        for (int qd = 0; qd < 5; qd++) {
            ulonglong2 w2 = wp[c * 5 + qd];
            FMA_F32X2(a0[2 * qd],     w2.x, d0, a0[2 * qd]);
            FMA_F32X2(a0[2 * qd + 1], w2.y, d0, a0[2 * qd + 1]);
        }
    }

    // unpack, store z, accumulate sumsq
    float qq[20];
#pragma unroll
    for (int p = 0; p < 10; p++) {
        float zlo, zhi;
        UNPACK2(zlo, zhi, a0[p]);
        int j0 = 2 * p, j1 = 2 * p + 1;
        g_z[(size_t)j0 * B + row] = zlo;
        g_z[(size_t)j1 * B + row] = zhi;
        qq[j0] = zlo * zlo;
        qq[j1] = zhi * zhi;
    }
#pragma unroll
    for (int j = 0; j < 20; j++) {
#pragma unroll
        for (int off = 16; off > 0; off >>= 1)
            qq[j] += __shfl_xor_sync(0xffffffffu, qq[j], off);
    }
    if ((threadIdx.x & 31) == 0) {
#pragma unroll
        for (int j = 0; j < 20; j++) atomicAdd(&sq[j], qq[j]);
    }
    __syncthreads();
    if (threadIdx.x < 20) atomicAdd(&g_stat2[threadIdx.x], sq[threadIdx.x]);
}

// ---------------- K4: finalize BN2 affine (mean computed analytically) -----
__global__ void k4_bn2(const float* __restrict__ g2, const float* __restrict__ b2,
                       float invB) {
    int j = threadIdx.x;
    if (j < 20) {
        float mu = 0.f;
#pragma unroll 8
        for (int c = 0; c < 128; c++)
            mu = fmaf(g_Wf[c * 20 + j], g_stat1[c], mu);
        mu *= invB;
        float var = fmaf(-mu, mu, g_stat2[j] * invB);
        float sc = g2[j] * rsqrtf(var + 1e-5f);
        g_s2[j] = sc;
        g_t2[j] = b2[j] - mu * sc;
    }
}

// ---------------- K5: BN2 + GELU + IT2 fuzzy + head ----------------
__global__ __launch_bounds__(256) void k5_fuzzy(float* __restrict__ out, int B) {
    __shared__ float4 fz[200];
    __shared__ float s2s[20], t2s[20], wrs[10];
    __shared__ float b0s;
    for (int i = threadIdx.x; i < 200; i += 256) fz[i] = g_fz[i];
    if (threadIdx.x < 20) { s2s[threadIdx.x] = g_s2[threadIdx.x]; t2s[threadIdx.x] = g_t2[threadIdx.x]; }
    if (threadIdx.x < 10) wrs[threadIdx.x] = g_wr[threadIdx.x];
    if (threadIdx.x == 0) b0s = g_b0;
    __syncthreads();

    int stride = gridDim.x * 256;
    for (int row = blockIdx.x * 256 + threadIdx.x; row < B; row += stride) {
        float z[20];
#pragma unroll
        for (int j = 0; j < 20; j++) {
            float v = fmaf(g_z[(size_t)j * B + row], s2s[j], t2s[j]);
            z[j] = 0.5f * v * (1.f + erff(v * 0.70710678118654752f));
        }
        float o = b0s;
#pragma unroll
        for (int r = 0; r < 10; r++) {
            float S = 0.f;
#pragma unroll
            for (int d = 0; d < 20; d++) {
                float4 p = fz[r * 20 + d];
                float df = z[d] - p.x;
                float d2 = df * df;
                S += ex2f(p.y * d2) + ex2f(p.z * d2);
            }
            o = fmaf(wrs[r], S, o);
        }
        out[row] = o;
    }
}

// ---------------- launcher ----------------
extern "C" void kernel_launch(void* const* d_in, const int* in_sizes, int n_in,
                              void* d_out, int out_size) {
    const float* x        = (const float*)d_in[0];
    const float* centres  = (const float*)d_in[1];
    const float* logw     = (const float*)d_in[2];
    const float* rbw      = (const float*)d_in[3];
    const float* linw     = (const float*)d_in[4];
    const float* pW       = (const float*)d_in[5];
    const float* pb       = (const float*)d_in[6];
    const float* bn1g     = (const float*)d_in[7];
    /* d_in[8] = bn1_beta  — cancels through BN2, unused */
    const float* fpW      = (const float*)d_in[9];
    /* d_in[10] = fp_b     — cancels through BN2, unused */
    const float* bn2g     = (const float*)d_in[11];
    const float* bn2b     = (const float*)d_in[12];
    const float* fzc      = (const float*)d_in[13];
    const float* lsu      = (const float*)d_in[14];
    const float* lsl      = (const float*)d_in[15];
    const float* hW       = (const float*)d_in[16];
    const float* hb       = (const float*)d_in[17];
    float* out = (float*)d_out;

    int B = in_sizes[0] / 64;
    float invB = 1.0f / (float)B;

    k0_zero<<<1, 256>>>();

    const int NB1 = 296;
    k1_kan<<<NB1, 256>>>(x, centres, logw, rbw, linw, pW, pb, B, NB1 * 32);

    k2_fold<<<1, 256>>>(bn1g, fpW, fzc, lsu, lsl, hW, hb, invB);

    k3_gemm<<<B / 256, 256>>>(B);

    k4_bn2<<<1, 32>>>(bn2g, bn2b, invB);

    int nb5 = (B + 255) / 256;
    k5_fuzzy<<<nb5, 256>>>(out, B);
}

// round 7
// speedup vs baseline: 1.7994x; 1.7994x over previous
#include <cuda_runtime.h>
#include <cstdint>

#define L2E 1.4426950408889634f
#define BMAX 131072

// ---------------- device scratch (static, no runtime alloc) ----------------
__device__ float g_act[64u * BMAX];     // act^T, channel-major [64][B], ch=g*8+f
__device__ float g_z[20u * BMAX];       // z~^T, channel-major [20][B]
__device__ float g_statA[352];          // per group: 8 sums + 36 sym-cov (44 each)
__device__ float g_stat2[20];           // sumsq[20] of z~
__device__ float g_M[64 * 20];          // combined weights, layout [ch][j]
__device__ float g_s2[20], g_t2[20];    // BN2 affine
__device__ float4 g_fz[200];            // (centre, au, al, 0) per (rule, dim)
__device__ float g_wr[10];              // head weight * 0.5/FIN
__device__ float g_b0;                  // head bias

__device__ __forceinline__ float ex2f(float x) {
    float y; asm("ex2.approx.ftz.f32 %0, %1;" : "=f"(y) : "f"(x)); return y;
}

#define FMA_F32X2(d, a, b, c) \
    asm("fma.rn.f32x2 %0, %1, %2, %3;" : "=l"(d) : "l"(a), "l"(b), "l"(c))
#define PACK_DUP(d, f) \
    asm("mov.b64 %0, {%1, %1};" : "=l"(d) : "f"(f))
#define UNPACK2(lo, hi, v) \
    asm("mov.b64 {%0, %1}, %2;" : "=f"(lo), "=f"(hi) : "l"(v))

// ---------------- K0: zero accumulators ----------------
__global__ void k0_zero() {
    int t = threadIdx.x;
    if (t < 352) g_statA[t] = 0.f;
    if (t < 20)  g_stat2[t] = 0.f;
}

// ---------------- K1: act = KAN-RBF(x), accumulate per-group act stats -----
// thread slot = (row-stream, group). slot%8 = group, slot/8 = starting row.
// RBF coefficients in registers; no projection here (folded into g_M).
__global__ __launch_bounds__(256, 2) void k1_kan(
    const float* __restrict__ x,
    const float* __restrict__ centres,   // [8][8]
    const float* __restrict__ logw,      // [8][8]
    const float* __restrict__ rbw,       // [8][8]
    const float* __restrict__ linw,      // [8]
    int B, int rowsInFlight)
{
    int slot = blockIdx.x * 256 + threadIdx.x;
    int g = slot & 7;
    int row0 = slot >> 3;

    float A[8], Bc[8], Gc[8], W[8];
#pragma unroll
    for (int k = 0; k < 8; k++) {
        float sig = __expf(logw[g * 8 + k]) + 1e-6f;
        float inv2 = 1.f / (sig * sig);
        float cc = centres[g * 8 + k];
        A[k] = -0.5f * L2E * inv2;
        Bc[k] = L2E * cc * inv2;
        Gc[k] = -0.5f * L2E * cc * cc * inv2;
        W[k] = rbw[g * 8 + k];
    }
    float lw = linw[g];

    float s[8], cv[36];
#pragma unroll
    for (int f = 0; f < 8; f++) s[f] = 0.f;
#pragma unroll
    for (int i = 0; i < 36; i++) cv[i] = 0.f;

    for (int row = row0; row < B; row += rowsInFlight) {
        const float4* xv = reinterpret_cast<const float4*>(x + (size_t)row * 64 + g * 8);
        float4 xa = xv[0], xb = xv[1];
        float xf[8] = {xa.x, xa.y, xa.z, xa.w, xb.x, xb.y, xb.z, xb.w};
        float act[8];
#pragma unroll
        for (int f = 0; f < 8; f++) {
            float xvv = xf[f];
            float x2 = xvv * xvv;
            float acc = 0.f;
#pragma unroll
            for (int k = 0; k < 8; k++) {
                float arg = fmaf(A[k], x2, fmaf(Bc[k], xvv, Gc[k]));
                acc = fmaf(W[k], ex2f(arg), acc);
            }
            act[f] = fmaf(lw, xvv, acc);
        }
#pragma unroll
        for (int f = 0; f < 8; f++) {
            g_act[(size_t)(g * 8 + f) * B + row] = act[f];
            s[f] += act[f];
        }
        int idx = 0;
#pragma unroll
        for (int f = 0; f < 8; f++)
#pragma unroll
            for (int f2 = 0; f2 <= f; f2++) {
                cv[idx] = fmaf(act[f], act[f2], cv[idx]);
                idx++;
            }
    }

    // reduce across the 4 lanes sharing the same group (xor 8, 16)
#pragma unroll
    for (int f = 0; f < 8; f++) {
        s[f] += __shfl_xor_sync(0xffffffffu, s[f], 8);
        s[f] += __shfl_xor_sync(0xffffffffu, s[f], 16);
    }
#pragma unroll
    for (int i = 0; i < 36; i++) {
        cv[i] += __shfl_xor_sync(0xffffffffu, cv[i], 8);
        cv[i] += __shfl_xor_sync(0xffffffffu, cv[i], 16);
    }
    __shared__ float sm[352];
    for (int i = threadIdx.x; i < 352; i += 256) sm[i] = 0.f;
    __syncthreads();
    if ((threadIdx.x & 31) < 8) {
#pragma unroll
        for (int f = 0; f < 8; f++) atomicAdd(&sm[g * 44 + f], s[f]);
#pragma unroll
        for (int i = 0; i < 36; i++) atomicAdd(&sm[g * 44 + 8 + i], cv[i]);
    }
    __syncthreads();
    for (int i = threadIdx.x; i < 352; i += 256)
        atomicAdd(&g_statA[i], sm[i]);
}

// ---------------- K2: BN1 var from cov; build M = Wf_folded * blockdiag(P) --
__global__ void k2_fold(
    const float* __restrict__ g1,        // bn1_gamma [128]
    const float* __restrict__ pW,        // [8][16][8]
    const float* __restrict__ fpW,       // [20][128]
    const float* __restrict__ fzc,       // [10][20]
    const float* __restrict__ lsu,       // [10][20]
    const float* __restrict__ lsl,       // [10][20]
    const float* __restrict__ hW,        // [1][10]
    const float* __restrict__ hb,        // [1]
    float invB)
{
    __shared__ float st[352];            // group stats
    __shared__ float s1sh[128];          // per-h-channel BN1 scale
    int t = threadIdx.x;
    for (int i = t; i < 352; i += blockDim.x) st[i] = g_statA[i];
    __syncthreads();

    if (t < 128) {
        int g = t >> 4, o = t & 15;
        float P[8];
#pragma unroll
        for (int f = 0; f < 8; f++) P[f] = pW[g * 128 + o * 8 + f];
        const float* gs = &st[g * 44];
        float sum_h = 0.f;
#pragma unroll
        for (int f = 0; f < 8; f++) sum_h = fmaf(P[f], gs[f], sum_h);
        // sumsq via symmetric covariance
        float ss = 0.f;
        int idx = 0;
#pragma unroll
        for (int f = 0; f < 8; f++)
#pragma unroll
            for (int f2 = 0; f2 <= f; f2++) {
                float c = gs[8 + idx];
                float w = (f == f2) ? P[f] * P[f] : 2.f * P[f] * P[f2];
                ss = fmaf(w, c, ss);
                idx++;
            }
        float mu = sum_h * invB;
        float var = fmaf(-mu, mu, ss * invB);
        s1sh[t] = g1[t] * rsqrtf(var + 1e-5f);
    }
    __syncthreads();

    // M[j][ch] = sum_o fpW[j][g*16+o] * s1[g*16+o] * P[g][o][f], stored [ch][j]
    for (int i = t; i < 1280; i += blockDim.x) {
        int ch = i / 20, j = i % 20;
        int g = ch >> 3, f = ch & 7;
        float acc = 0.f;
#pragma unroll
        for (int o = 0; o < 16; o++) {
            int c = g * 16 + o;
            acc = fmaf(fpW[j * 128 + c] * s1sh[c], pW[g * 128 + o * 8 + f], acc);
        }
        g_M[ch * 20 + j] = acc;
    }

    for (int i = t; i < 200; i += blockDim.x) {
        float su = __expf(lsu[i]) + 1e-6f;
        float sl = fminf(__expf(lsl[i]) + 1e-6f, 0.9f * su);
        float4 v;
        v.x = fzc[i];
        v.y = -0.5f * L2E / (su * su);
        v.z = -0.5f * L2E / (sl * sl);
        v.w = 0.f;
        g_fz[i] = v;
    }
    if (t < 10) g_wr[t] = hW[t] * (0.5f / 20.f);
    if (t == 0) g_b0 = hb[0];
}

// ---------------- K3: z~ = act @ M^T (f32x2 packed), sumsq(z~) stats -------
// ONE row per thread: grid = B/256 blocks of 256 threads.
__global__ __launch_bounds__(256) void k3_gemm(int B) {
    __shared__ float ws[1280];           // M [ch][j]
    __shared__ float sq[20];
    for (int i = threadIdx.x; i < 1280; i += 256) ws[i] = g_M[i];
    if (threadIdx.x < 20) sq[threadIdx.x] = 0.f;
    __syncthreads();
    const ulonglong2* wp = reinterpret_cast<const ulonglong2*>(ws);

    int row = blockIdx.x * 256 + threadIdx.x;

    unsigned long long a0[10];
#pragma unroll
    for (int p = 0; p < 10; p++) a0[p] = 0ull;

#pragma unroll 16
    for (int ch = 0; ch < 64; ch++) {
        float h = g_act[(size_t)ch * B + row];
        unsigned long long d0;
        PACK_DUP(d0, h);
#pragma unroll
        for (int qd = 0; qd < 5; qd++) {
            ulonglong2 w2 = wp[ch * 5 + qd];
            FMA_F32X2(a0[2 * qd],     w2.x, d0, a0[2 * qd]);
            FMA_F32X2(a0[2 * qd + 1], w2.y, d0, a0[2 * qd + 1]);
        }
    }

    // unpack, store z, accumulate sumsq
    float qq[20];
#pragma unroll
    for (int p = 0; p < 10; p++) {
        float zlo, zhi;
        UNPACK2(zlo, zhi, a0[p]);
        int j0 = 2 * p, j1 = 2 * p + 1;
        g_z[(size_t)j0 * B + row] = zlo;
        g_z[(size_t)j1 * B + row] = zhi;
        qq[j0] = zlo * zlo;
        qq[j1] = zhi * zhi;
    }
#pragma unroll
    for (int j = 0; j < 20; j++) {
#pragma unroll
        for (int off = 16; off > 0; off >>= 1)
            qq[j] += __shfl_xor_sync(0xffffffffu, qq[j], off);
    }
    if ((threadIdx.x & 31) == 0) {
#pragma unroll
        for (int j = 0; j < 20; j++) atomicAdd(&sq[j], qq[j]);
    }
    __syncthreads();
    if (threadIdx.x < 20) atomicAdd(&g_stat2[threadIdx.x], sq[threadIdx.x]);
}

// ---------------- K4: finalize BN2 affine (mean computed analytically) -----
__global__ void k4_bn2(const float* __restrict__ g2, const float* __restrict__ b2,
                       float invB) {
    int j = threadIdx.x;
    if (j < 20) {
        float mu = 0.f;
#pragma unroll 8
        for (int ch = 0; ch < 64; ch++) {
            int g = ch >> 3, f = ch & 7;
            mu = fmaf(g_M[ch * 20 + j], g_statA[g * 44 + f], mu);
        }
        mu *= invB;
        float var = fmaf(-mu, mu, g_stat2[j] * invB);
        float sc = g2[j] * rsqrtf(var + 1e-5f);
        g_s2[j] = sc;
        g_t2[j] = b2[j] - mu * sc;
    }
}

// ---------------- K5: BN2 + GELU + IT2 fuzzy + head ----------------
__global__ __launch_bounds__(256) void k5_fuzzy(float* __restrict__ out, int B) {
    __shared__ float4 fz[200];
    __shared__ float s2s[20], t2s[20], wrs[10];
    __shared__ float b0s;
    for (int i = threadIdx.x; i < 200; i += 256) fz[i] = g_fz[i];
    if (threadIdx.x < 20) { s2s[threadIdx.x] = g_s2[threadIdx.x]; t2s[threadIdx.x] = g_t2[threadIdx.x]; }
    if (threadIdx.x < 10) wrs[threadIdx.x] = g_wr[threadIdx.x];
    if (threadIdx.x == 0) b0s = g_b0;
    __syncthreads();

    int stride = gridDim.x * 256;
    for (int row = blockIdx.x * 256 + threadIdx.x; row < B; row += stride) {
        float z[20];
#pragma unroll
        for (int j = 0; j < 20; j++) {
            float v = fmaf(g_z[(size_t)j * B + row], s2s[j], t2s[j]);
            z[j] = 0.5f * v * (1.f + erff(v * 0.70710678118654752f));
        }
        float o = b0s;
#pragma unroll
        for (int r = 0; r < 10; r++) {
            float S = 0.f;
#pragma unroll
            for (int d = 0; d < 20; d++) {
                float4 p = fz[r * 20 + d];
                float df = z[d] - p.x;
                float d2 = df * df;
                S += ex2f(p.y * d2) + ex2f(p.z * d2);
            }
            o = fmaf(wrs[r], S, o);
        }
        out[row] = o;
    }
}

// ---------------- launcher ----------------
extern "C" void kernel_launch(void* const* d_in, const int* in_sizes, int n_in,
                              void* d_out, int out_size) {
    const float* x        = (const float*)d_in[0];
    const float* centres  = (const float*)d_in[1];
    const float* logw     = (const float*)d_in[2];
    const float* rbw      = (const float*)d_in[3];
    const float* linw     = (const float*)d_in[4];
    const float* pW       = (const float*)d_in[5];
    /* d_in[6] = proj_b   — folds into z~ constant, cancels through BN2 */
    const float* bn1g     = (const float*)d_in[7];
    /* d_in[8] = bn1_beta  — cancels through BN2, unused */
    const float* fpW      = (const float*)d_in[9];
    /* d_in[10] = fp_b     — cancels through BN2, unused */
    const float* bn2g     = (const float*)d_in[11];
    const float* bn2b     = (const float*)d_in[12];
    const float* fzc      = (const float*)d_in[13];
    const float* lsu      = (const float*)d_in[14];
    const float* lsl      = (const float*)d_in[15];
    const float* hW       = (const float*)d_in[16];
    const float* hb       = (const float*)d_in[17];
    float* out = (float*)d_out;

    int B = in_sizes[0] / 64;
    float invB = 1.0f / (float)B;

    k0_zero<<<1, 512>>>();

    const int NB1 = 296;
    k1_kan<<<NB1, 256>>>(x, centres, logw, rbw, linw, B, NB1 * 32);

    k2_fold<<<1, 256>>>(bn1g, pW, fpW, fzc, lsu, lsl, hW, hb, invB);

    k3_gemm<<<B / 256, 256>>>(B);

    k4_bn2<<<1, 32>>>(bn2g, bn2b, invB);

    int nb5 = (B + 255) / 256;
    k5_fuzzy<<<nb5, 256>>>(out, B);
}

// round 9
// speedup vs baseline: 1.8166x; 1.0095x over previous
#include <cuda_runtime.h>
#include <cstdint>

#define L2E 1.4426950408889634f
#define BMAX 131072

// ---------------- device scratch (static, no runtime alloc) ----------------
// act in quad-interleaved layout: [16 quads][B][4], quad q holds channels 4q..4q+3
__device__ float g_act[64u * BMAX];
__device__ float g_z[20u * BMAX];       // z~^T, channel-major [20][B]
__device__ float g_statA[352];          // per group: 8 sums + 36 sym-cov (44 each)
__device__ float g_stat2[20];           // sumsq[20] of z~
__device__ float g_M[64 * 20];          // combined weights, layout [ch][j]
__device__ float g_s2[20], g_t2[20];    // BN2 affine
__device__ float4 g_fz[200];            // (centre, au, al, 0) per (rule, dim)
__device__ float g_wr[10];              // head weight * 0.5/FIN
__device__ float g_b0;                  // head bias

__device__ __forceinline__ float ex2f(float x) {
    float y; asm("ex2.approx.ftz.f32 %0, %1;" : "=f"(y) : "f"(x)); return y;
}

#define FMA_F32X2(d, a, b, c) \
    asm("fma.rn.f32x2 %0, %1, %2, %3;" : "=l"(d) : "l"(a), "l"(b), "l"(c))
#define PACK_DUP(d, f) \
    asm("mov.b64 %0, {%1, %1};" : "=l"(d) : "f"(f))
#define UNPACK2(lo, hi, v) \
    asm("mov.b64 {%0, %1}, %2;" : "=f"(lo), "=f"(hi) : "l"(v))

// ---------------- K0: zero accumulators ----------------
__global__ void k0_zero() {
    int t = threadIdx.x;
    if (t < 352) g_statA[t] = 0.f;
    if (t < 20)  g_stat2[t] = 0.f;
}

// ---------------- K1: act = KAN-RBF(x), accumulate per-group act stats -----
// thread slot = (row-stream, group). slot%8 = group, slot/8 = starting row.
// act stored quad-interleaved: 2 x STG.128 per task, coalescable.
__global__ __launch_bounds__(256, 2) void k1_kan(
    const float* __restrict__ x,
    const float* __restrict__ centres,   // [8][8]
    const float* __restrict__ logw,      // [8][8]
    const float* __restrict__ rbw,       // [8][8]
    const float* __restrict__ linw,      // [8]
    int B, int rowsInFlight)
{
    int slot = blockIdx.x * 256 + threadIdx.x;
    int g = slot & 7;
    int row0 = slot >> 3;
    size_t B4 = (size_t)B * 4;

    float A[8], Bc[8], Gc[8], W[8];
#pragma unroll
    for (int k = 0; k < 8; k++) {
        float sig = __expf(logw[g * 8 + k]) + 1e-6f;
        float inv2 = 1.f / (sig * sig);
        float cc = centres[g * 8 + k];
        A[k] = -0.5f * L2E * inv2;
        Bc[k] = L2E * cc * inv2;
        Gc[k] = -0.5f * L2E * cc * cc * inv2;
        W[k] = rbw[g * 8 + k];
    }
    float lw = linw[g];

    float s[8], cv[36];
#pragma unroll
    for (int f = 0; f < 8; f++) s[f] = 0.f;
#pragma unroll
    for (int i = 0; i < 36; i++) cv[i] = 0.f;

    for (int row = row0; row < B; row += rowsInFlight) {
        const float4* xv = reinterpret_cast<const float4*>(x + (size_t)row * 64 + g * 8);
        float4 xa = xv[0], xb = xv[1];
        float xf[8] = {xa.x, xa.y, xa.z, xa.w, xb.x, xb.y, xb.z, xb.w};
        float act[8];
#pragma unroll
        for (int f = 0; f < 8; f++) {
            float xvv = xf[f];
            float x2 = xvv * xvv;
            float acc = 0.f;
#pragma unroll
            for (int k = 0; k < 8; k++) {
                float arg = fmaf(A[k], x2, fmaf(Bc[k], xvv, Gc[k]));
                acc = fmaf(W[k], ex2f(arg), acc);
            }
            act[f] = fmaf(lw, xvv, acc);
        }
        // quad-interleaved store: q = 2g and 2g+1
        float4 v0 = make_float4(act[0], act[1], act[2], act[3]);
        float4 v1 = make_float4(act[4], act[5], act[6], act[7]);
        *reinterpret_cast<float4*>(&g_act[(size_t)(2 * g) * B4 + (size_t)row * 4]) = v0;
        *reinterpret_cast<float4*>(&g_act[(size_t)(2 * g + 1) * B4 + (size_t)row * 4]) = v1;
#pragma unroll
        for (int f = 0; f < 8; f++) s[f] += act[f];
        int idx = 0;
#pragma unroll
        for (int f = 0; f < 8; f++)
#pragma unroll
            for (int f2 = 0; f2 <= f; f2++) {
                cv[idx] = fmaf(act[f], act[f2], cv[idx]);
                idx++;
            }
    }

    // reduce across the 4 lanes sharing the same group (xor 8, 16)
#pragma unroll
    for (int f = 0; f < 8; f++) {
        s[f] += __shfl_xor_sync(0xffffffffu, s[f], 8);
        s[f] += __shfl_xor_sync(0xffffffffu, s[f], 16);
    }
#pragma unroll
    for (int i = 0; i < 36; i++) {
        cv[i] += __shfl_xor_sync(0xffffffffu, cv[i], 8);
        cv[i] += __shfl_xor_sync(0xffffffffu, cv[i], 16);
    }
    __shared__ float sm[352];
    for (int i = threadIdx.x; i < 352; i += 256) sm[i] = 0.f;
    __syncthreads();
    if ((threadIdx.x & 31) < 8) {
#pragma unroll
        for (int f = 0; f < 8; f++) atomicAdd(&sm[g * 44 + f], s[f]);
#pragma unroll
        for (int i = 0; i < 36; i++) atomicAdd(&sm[g * 44 + 8 + i], cv[i]);
    }
    __syncthreads();
    for (int i = threadIdx.x; i < 352; i += 256)
        atomicAdd(&g_statA[i], sm[i]);
}

// ---------------- K2: BN1 var from cov; build M = Wf_folded * blockdiag(P) --
__global__ void k2_fold(
    const float* __restrict__ g1,        // bn1_gamma [128]
    const float* __restrict__ pW,        // [8][16][8]
    const float* __restrict__ fpW,       // [20][128]
    const float* __restrict__ fzc,       // [10][20]
    const float* __restrict__ lsu,       // [10][20]
    const float* __restrict__ lsl,       // [10][20]
    const float* __restrict__ hW,        // [1][10]
    const float* __restrict__ hb,        // [1]
    float invB)
{
    __shared__ float st[352];            // group stats
    __shared__ float s1sh[128];          // per-h-channel BN1 scale
    int t = threadIdx.x;
    for (int i = t; i < 352; i += blockDim.x) st[i] = g_statA[i];
    __syncthreads();

    if (t < 128) {
        int g = t >> 4, o = t & 15;
        float P[8];
#pragma unroll
        for (int f = 0; f < 8; f++) P[f] = pW[g * 128 + o * 8 + f];
        const float* gs = &st[g * 44];
        float sum_h = 0.f;
#pragma unroll
        for (int f = 0; f < 8; f++) sum_h = fmaf(P[f], gs[f], sum_h);
        float ss = 0.f;
        int idx = 0;
#pragma unroll
        for (int f = 0; f < 8; f++)
#pragma unroll
            for (int f2 = 0; f2 <= f; f2++) {
                float c = gs[8 + idx];
                float w = (f == f2) ? P[f] * P[f] : 2.f * P[f] * P[f2];
                ss = fmaf(w, c, ss);
                idx++;
            }
        float mu = sum_h * invB;
        float var = fmaf(-mu, mu, ss * invB);
        s1sh[t] = g1[t] * rsqrtf(var + 1e-5f);
    }
    __syncthreads();

    // M[j][ch] = sum_o fpW[j][g*16+o] * s1[g*16+o] * P[g][o][f], stored [ch][j]
    for (int i = t; i < 1280; i += blockDim.x) {
        int ch = i / 20, j = i % 20;
        int g = ch >> 3, f = ch & 7;
        float acc = 0.f;
#pragma unroll
        for (int o = 0; o < 16; o++) {
            int c = g * 16 + o;
            acc = fmaf(fpW[j * 128 + c] * s1sh[c], pW[g * 128 + o * 8 + f], acc);
        }
        g_M[ch * 20 + j] = acc;
    }

    for (int i = t; i < 200; i += blockDim.x) {
        float su = __expf(lsu[i]) + 1e-6f;
        float sl = fminf(__expf(lsl[i]) + 1e-6f, 0.9f * su);
        float4 v;
        v.x = fzc[i];
        v.y = -0.5f * L2E / (su * su);
        v.z = -0.5f * L2E / (sl * sl);
        v.w = 0.f;
        g_fz[i] = v;
    }
    if (t < 10) g_wr[t] = hW[t] * (0.5f / 20.f);
    if (t == 0) g_b0 = hb[0];
}

// ---------------- K3: z~ = act @ M^T (f32x2 packed), sumsq(z~) stats -------
// ONE row per thread. act read as 16 coalesced LDG.128 (quad layout).
__global__ __launch_bounds__(256) void k3_gemm(int B) {
    __shared__ float ws[1280];           // M [ch][j]
    __shared__ float sq[20];
    for (int i = threadIdx.x; i < 1280; i += 256) ws[i] = g_M[i];
    if (threadIdx.x < 20) sq[threadIdx.x] = 0.f;
    __syncthreads();
    const ulonglong2* wp = reinterpret_cast<const ulonglong2*>(ws);

    int row = blockIdx.x * 256 + threadIdx.x;
    size_t B4 = (size_t)B * 4;

    unsigned long long a0[10];
#pragma unroll
    for (int p = 0; p < 10; p++) a0[p] = 0ull;

#pragma unroll
    for (int q = 0; q < 16; q++) {
        float4 av = *reinterpret_cast<const float4*>(&g_act[(size_t)q * B4 + (size_t)row * 4]);
        float af[4] = {av.x, av.y, av.z, av.w};
#pragma unroll
        for (int i = 0; i < 4; i++) {
            int ch = q * 4 + i;
            unsigned long long d0;
            PACK_DUP(d0, af[i]);
#pragma unroll
            for (int qd = 0; qd < 5; qd++) {
                ulonglong2 w2 = wp[ch * 5 + qd];
                FMA_F32X2(a0[2 * qd],     w2.x, d0, a0[2 * qd]);
                FMA_F32X2(a0[2 * qd + 1], w2.y, d0, a0[2 * qd + 1]);
            }
        }
    }

    // unpack, store z, accumulate sumsq
    float qq[20];
#pragma unroll
    for (int p = 0; p < 10; p++) {
        float zlo, zhi;
        UNPACK2(zlo, zhi, a0[p]);
        int j0 = 2 * p, j1 = 2 * p + 1;
        g_z[(size_t)j0 * B + row] = zlo;
        g_z[(size_t)j1 * B + row] = zhi;
        qq[j0] = zlo * zlo;
        qq[j1] = zhi * zhi;
    }
#pragma unroll
    for (int j = 0; j < 20; j++) {
#pragma unroll
        for (int off = 16; off > 0; off >>= 1)
            qq[j] += __shfl_xor_sync(0xffffffffu, qq[j], off);
    }
    if ((threadIdx.x & 31) == 0) {
#pragma unroll
        for (int j = 0; j < 20; j++) atomicAdd(&sq[j], qq[j]);
    }
    __syncthreads();
    if (threadIdx.x < 20) atomicAdd(&g_stat2[threadIdx.x], sq[threadIdx.x]);
}

// ---------------- K4: finalize BN2 affine (mean computed analytically) -----
__global__ void k4_bn2(const float* __restrict__ g2, const float* __restrict__ b2,
                       float invB) {
    int j = threadIdx.x;
    if (j < 20) {
        float mu = 0.f;
#pragma unroll 8
        for (int ch = 0; ch < 64; ch++) {
            int g = ch >> 3, f = ch & 7;
            mu = fmaf(g_M[ch * 20 + j], g_statA[g * 44 + f], mu);
        }
        mu *= invB;
        float var = fmaf(-mu, mu, g_stat2[j] * invB);
        float sc = g2[j] * rsqrtf(var + 1e-5f);
        g_s2[j] = sc;
        g_t2[j] = b2[j] - mu * sc;
    }
}

// ---------------- K5: BN2 + GELU + IT2 fuzzy + head ----------------
__global__ __launch_bounds__(256) void k5_fuzzy(float* __restrict__ out, int B) {
    __shared__ float4 fz[200];
    __shared__ float s2s[20], t2s[20], wrs[10];
    __shared__ float b0s;
    for (int i = threadIdx.x; i < 200; i += 256) fz[i] = g_fz[i];
    if (threadIdx.x < 20) { s2s[threadIdx.x] = g_s2[threadIdx.x]; t2s[threadIdx.x] = g_t2[threadIdx.x]; }
    if (threadIdx.x < 10) wrs[threadIdx.x] = g_wr[threadIdx.x];
    if (threadIdx.x == 0) b0s = g_b0;
    __syncthreads();

    int stride = gridDim.x * 256;
    for (int row = blockIdx.x * 256 + threadIdx.x; row < B; row += stride) {
        float z[20];
#pragma unroll
        for (int j = 0; j < 20; j++) {
            float v = fmaf(g_z[(size_t)j * B + row], s2s[j], t2s[j]);
            z[j] = 0.5f * v * (1.f + erff(v * 0.70710678118654752f));
        }
        float o = b0s;
#pragma unroll
        for (int r = 0; r < 10; r++) {
            float S = 0.f;
#pragma unroll
            for (int d = 0; d < 20; d++) {
                float4 p = fz[r * 20 + d];
                float df = z[d] - p.x;
                float d2 = df * df;
                S += ex2f(p.y * d2) + ex2f(p.z * d2);
            }
            o = fmaf(wrs[r], S, o);
        }
        out[row] = o;
    }
}

// ---------------- launcher ----------------
extern "C" void kernel_launch(void* const* d_in, const int* in_sizes, int n_in,
                              void* d_out, int out_size) {
    const float* x        = (const float*)d_in[0];
    const float* centres  = (const float*)d_in[1];
    const float* logw     = (const float*)d_in[2];
    const float* rbw      = (const float*)d_in[3];
    const float* linw     = (const float*)d_in[4];
    const float* pW       = (const float*)d_in[5];
    /* d_in[6] = proj_b   — folds into z~ constant, cancels through BN2 */
    const float* bn1g     = (const float*)d_in[7];
    /* d_in[8] = bn1_beta  — cancels through BN2, unused */
    const float* fpW      = (const float*)d_in[9];
    /* d_in[10] = fp_b     — cancels through BN2, unused */
    const float* bn2g     = (const float*)d_in[11];
    const float* bn2b     = (const float*)d_in[12];
    const float* fzc      = (const float*)d_in[13];
    const float* lsu      = (const float*)d_in[14];
    const float* lsl      = (const float*)d_in[15];
    const float* hW       = (const float*)d_in[16];
    const float* hb       = (const float*)d_in[17];
    float* out = (float*)d_out;

    int B = in_sizes[0] / 64;
    float invB = 1.0f / (float)B;

    k0_zero<<<1, 512>>>();

    const int NB1 = 296;
    k1_kan<<<NB1, 256>>>(x, centres, logw, rbw, linw, B, NB1 * 32);

    k2_fold<<<1, 256>>>(bn1g, pW, fpW, fzc, lsu, lsl, hW, hb, invB);

    k3_gemm<<<B / 256, 256>>>(B);

    k4_bn2<<<1, 32>>>(bn2g, bn2b, invB);

    int nb5 = (B + 255) / 256;
    k5_fuzzy<<<nb5, 256>>>(out, B);
}